// round 16
// baseline (speedup 1.0000x reference)
#include <cuda_runtime.h>
#include <math.h>

// KarplusStrongResonator: (1 + q) Y = X, q = a1 z^-d1 + a2 z^-d2,
// d1 = 61 + argmax(delay_param + gumbel), d2 = 61 + ((argmax+1) % 360).
// Identity: (1 - q^8) Y = (1-q)(1+q^2)(1+q^4) X.
// Fast path (d2 == d1+1):
//   phase 1:  B = (1 - q + q^2 - q^3) X       (fused parallel pass, per row)
//   phase 2:  y = (1+q^4)B + q^8 y per chunk  (both rows interleaved per thread)
// TWO rows per CTA (grid 64): doubles independent ILP per SM and amortizes
// every chunk barrier over 2x the work — the kernel is latency-bound.

#define T_LEN 8192
#define B_ROWS 128
#define ROWS_PER_CTA 2
#define NDELAY 360
#define NT 512
#define NWARP (NT / 32)
#define PAD 3360           // == 8*419 + 8 (max q^8 lag), multiple of 4
#define ROW_STRIDE (2 * (PAD + T_LEN))   // floats per row (A pad+data, B pad+data)

__device__ __forceinline__ float4 lds4(const float* p) {
    return *reinterpret_cast<const float4*>(p);
}

// Fused pass: B[t] = A[t] - q A + q^2 A - q^3 A (contiguous windows, d2=d1+1).
// Window W_k starts at aligned offset off_k = k*(d1+1) + M_k, M_k = (4-(k*R&3))&3.
template<int R>
__device__ __forceinline__ void fused_pass(const float* __restrict__ A,
                                           float* __restrict__ B,
                                           float a1, float a2, int d1, int tid)
{
    constexpr int M1 = (4 - (R & 3)) & 3;
    constexpr int M2 = (4 - ((2 * R) & 3)) & 3;
    constexpr int M3 = (4 - ((3 * R) & 3)) & 3;
    constexpr int NV1 = (M1 + 1 + 4 + 3) / 4;
    constexpr int NV2 = (M2 + 2 + 4 + 3) / 4;
    constexpr int NV3 = (M3 + 3 + 4 + 3) / 4;
    const int off1 = (d1 + 1) + M1;
    const int off2 = 2 * (d1 + 1) + M2;
    const int off3 = 3 * (d1 + 1) + M3;

    const float c10 = -a2,            c11 = -a1;
    const float c20 =  a2 * a2,       c21 = 2.f * a1 * a2,  c22 = a1 * a1;
    const float c30 = -a2 * a2 * a2,  c31 = -3.f * a1 * a2 * a2,
                c32 = -3.f * a1 * a1 * a2, c33 = -a1 * a1 * a1;

    for (int t0 = 4 * tid; t0 < T_LEN; t0 += 4 * NT) {
        float4 c = lds4(&A[t0]);
        float W1[NV1 * 4], W2[NV2 * 4], W3[NV3 * 4];
        #pragma unroll
        for (int v = 0; v < NV1; v++) {
            float4 w = lds4(&A[t0 - off1 + 4 * v]);
            W1[4*v] = w.x; W1[4*v+1] = w.y; W1[4*v+2] = w.z; W1[4*v+3] = w.w;
        }
        #pragma unroll
        for (int v = 0; v < NV2; v++) {
            float4 w = lds4(&A[t0 - off2 + 4 * v]);
            W2[4*v] = w.x; W2[4*v+1] = w.y; W2[4*v+2] = w.z; W2[4*v+3] = w.w;
        }
        #pragma unroll
        for (int v = 0; v < NV3; v++) {
            float4 w = lds4(&A[t0 - off3 + 4 * v]);
            W3[4*v] = w.x; W3[4*v+1] = w.y; W3[4*v+2] = w.z; W3[4*v+3] = w.w;
        }
        float cv[4] = {c.x, c.y, c.z, c.w};
        float r[4];
        #pragma unroll
        for (int s = 0; s < 4; s++) {
            float v0 = fmaf(c10, W1[M1 + s],     cv[s]);
            float v1 = fmaf(c11, W1[M1 + s + 1], c20 * W2[M2 + s]);
            float v2 = fmaf(c21, W2[M2 + s + 1], c22 * W2[M2 + s + 2]);
            float v3 = fmaf(c30, W3[M3 + s],     c31 * W3[M3 + s + 1]);
            float v4 = fmaf(c32, W3[M3 + s + 2], c33 * W3[M3 + s + 3]);
            r[s] = (v0 + v1) + (v2 + (v3 + v4));
        }
        *reinterpret_cast<float4*>(&B[t0]) = make_float4(r[0], r[1], r[2], r[3]);
    }
}

__global__ __launch_bounds__(NT, 1)
void ks_resonator_kernel(const float* __restrict__ x,
                         const float* __restrict__ gumbel,
                         const float* __restrict__ dparam,
                         const float* __restrict__ fgain,
                         const float* __restrict__ refl,
                         float* __restrict__ out)
{
    extern __shared__ float smem[];
    // Per row r: A_r = smem + r*ROW_STRIDE + PAD        (x, then y)
    //            B_r = smem + r*ROW_STRIDE + 2*PAD + T  (fused-pass output)
    float* A0 = smem + PAD;
    float* B0 = smem + 2 * PAD + T_LEN;
    float* A1 = smem + ROW_STRIDE + PAD;
    float* B1 = smem + ROW_STRIDE + 2 * PAD + T_LEN;

    __shared__ float red_v[NWARP];
    __shared__ int   red_i[NWARP];
    __shared__ float s_a1, s_a2;
    __shared__ int   s_d1, s_d2;

    const int tid  = threadIdx.x;
    const int lane = tid & 31;
    const int wid  = tid >> 5;
    const int row0 = blockIdx.x * ROWS_PER_CTA;

    // ---- async prefetch: row0 (group 0) then row1 (group 1) ----
    {
        const char* g0 = (const char*)(x + (size_t)row0 * T_LEN);
        const char* g1 = (const char*)(x + (size_t)(row0 + 1) * T_LEN);
        #pragma unroll
        for (int i = tid; i < T_LEN / 4; i += NT) {
            unsigned sdst = (unsigned)__cvta_generic_to_shared(A0 + 4 * i);
            asm volatile("cp.async.cg.shared.global [%0], [%1], 16;\n"
                         :: "r"(sdst), "l"(g0 + 16 * (size_t)i));
        }
        asm volatile("cp.async.commit_group;\n");
        #pragma unroll
        for (int i = tid; i < T_LEN / 4; i += NT) {
            unsigned sdst = (unsigned)__cvta_generic_to_shared(A1 + 4 * i);
            asm volatile("cp.async.cg.shared.global [%0], [%1], 16;\n"
                         :: "r"(sdst), "l"(g1 + 16 * (size_t)i));
        }
        asm volatile("cp.async.commit_group;\n");
    }

    // ---- zero all four pad regions (overlaps the cp.async fetches) ----
    {
        float4 z = make_float4(0.f, 0.f, 0.f, 0.f);
        float4* p0 = reinterpret_cast<float4*>(smem);                              // A0 pad
        float4* p1 = reinterpret_cast<float4*>(smem + PAD + T_LEN);                // B0 pad
        float4* p2 = reinterpret_cast<float4*>(smem + ROW_STRIDE);                 // A1 pad
        float4* p3 = reinterpret_cast<float4*>(smem + ROW_STRIDE + PAD + T_LEN);   // B1 pad
        #pragma unroll
        for (int i = tid; i < PAD / 4; i += NT) { p0[i] = z; p1[i] = z; p2[i] = z; p3[i] = z; }
    }

    // ---- argmax(delay_param + gumbel) via shuffles (overlapped) ----
    {
        float v = -INFINITY;
        int   idx = 0;
        if (tid < NDELAY) { v = dparam[tid] + gumbel[tid]; idx = tid; }
        #pragma unroll
        for (int off = 16; off > 0; off >>= 1) {
            float v2 = __shfl_down_sync(0xffffffffu, v, off);
            int   i2 = __shfl_down_sync(0xffffffffu, idx, off);
            if (v2 > v || (v2 == v && i2 < idx)) { v = v2; idx = i2; }
        }
        if (lane == 0) { red_v[wid] = v; red_i[wid] = idx; }
        __syncthreads();   // pads + partials visible
        if (wid == 0) {
            float vv = (lane < NWARP) ? red_v[lane] : -INFINITY;
            int   ii = (lane < NWARP) ? red_i[lane] : 0;
            #pragma unroll
            for (int off = 8; off > 0; off >>= 1) {
                float v2 = __shfl_down_sync(0xffffffffu, vv, off);
                int   i2 = __shfl_down_sync(0xffffffffu, ii, off);
                if (v2 > vv || (v2 == vv && i2 < ii)) { vv = v2; ii = i2; }
            }
            if (lane == 0) {
                int j = ii;
                float k1 = tanhf(tanhf(refl[0]));  // resonant_activation(tanh(rc), tau=0)
                float k2 = tanhf(tanhf(refl[1]));
                float a1 = k1 * (1.0f - k2);
                float a2 = fminf(fmaxf(k2, -0.999f), 0.999f);
                float a1b = 0.999f - fabsf(a2);
                a1 = fminf(fmaxf(a1, -a1b), a1b);
                float g = powf(1.0f / (1.0f + expf(-fgain[0])), 0.45f);
                s_a1 = a1 * g;
                s_a2 = a2 * g;
                s_d1 = 61 + j;
                s_d2 = 61 + ((j + 1) % NDELAY);
            }
        }
    }

    // ---- wait row0 data + coefficients ----
    asm volatile("cp.async.wait_group 1;\n");
    __syncthreads();

    const float a1 = s_a1, a2 = s_a2;
    const int d1 = s_d1, d2 = s_d2;

    // q^4, q^8 tap arrays: qNc[k] = C(N,k) a1^k a2^(N-k)
    float q4c[5], q8c[9];
    {
        float p1[9], p2[9];
        p1[0] = 1.f; p2[0] = 1.f;
        #pragma unroll
        for (int i = 1; i < 9; i++) { p1[i] = p1[i-1] * a1; p2[i] = p2[i-1] * a2; }
        const float C8[9] = {1.f, 8.f, 28.f, 56.f, 70.f, 56.f, 28.f, 8.f, 1.f};
        const float C4[5] = {1.f, 4.f, 6.f, 4.f, 1.f};
        #pragma unroll
        for (int k = 0; k < 9; k++) q8c[k] = C8[k] * p1[k] * p2[8 - k];
        #pragma unroll
        for (int k = 0; k < 5; k++) q4c[k] = C4[k] * p1[k] * p2[4 - k];
    }

    float* orow0 = out + (size_t)row0 * T_LEN;
    float* orow1 = out + (size_t)(row0 + 1) * T_LEN;

    if (d2 == d1 + 1) {
        // ================= FAST PATH =================
        const int R = (d1 + 1) & 3;

        // fused pass row0 (overlaps row1 DRAM arrival)
        switch (R) {
            case 0: fused_pass<0>(A0, B0, a1, a2, d1, tid); break;
            case 1: fused_pass<1>(A0, B0, a1, a2, d1, tid); break;
            case 2: fused_pass<2>(A0, B0, a1, a2, d1, tid); break;
            default: fused_pass<3>(A0, B0, a1, a2, d1, tid); break;
        }
        asm volatile("cp.async.wait_group 0;\n");
        __syncthreads();
        switch (R) {
            case 0: fused_pass<0>(A1, B1, a1, a2, d1, tid); break;
            case 1: fused_pass<1>(A1, B1, a1, a2, d1, tid); break;
            case 2: fused_pass<2>(A1, B1, a1, a2, d1, tid); break;
            default: fused_pass<3>(A1, B1, a1, a2, d1, tid); break;
        }
        __syncthreads();

        // recurrence, both rows interleaved: y = B + q^4 B + q^8 y  (y over A)
        {
            const int off4 = 4 * d1 + 4;     // aligned
            const int off8 = 8 * d1 + 8;     // aligned
            const int Cq   = 8 * d1;         // chunk (mult of 4)
            const int nw_act = min(NWARP, (d1 + 15) >> 4);
            const int nthr   = nw_act * 32;
            if (wid < nw_act) {
                for (int base = 0; base < T_LEN; base += Cq) {
                    const int end = min(base + Cq, T_LEN);
                    for (int t0 = base + 4 * tid; t0 < end; t0 += 4 * nthr) {
                        // row0 loads
                        float4 cv0 = lds4(&B0[t0]);
                        float4 p00 = lds4(&B0[t0 - off4]);
                        float4 p01 = lds4(&B0[t0 - off4 + 4]);
                        float4 y00 = lds4(&A0[t0 - off8]);
                        float4 y01 = lds4(&A0[t0 - off8 + 4]);
                        float4 y02 = lds4(&A0[t0 - off8 + 8]);
                        // row1 loads (independent — issue before any FMA retires)
                        float4 cv1 = lds4(&B1[t0]);
                        float4 p10 = lds4(&B1[t0 - off4]);
                        float4 p11 = lds4(&B1[t0 - off4 + 4]);
                        float4 y10 = lds4(&A1[t0 - off8]);
                        float4 y11 = lds4(&A1[t0 - off8 + 4]);
                        float4 y12 = lds4(&A1[t0 - off8 + 8]);

                        float W40[8]  = {p00.x, p00.y, p00.z, p00.w,
                                         p01.x, p01.y, p01.z, p01.w};
                        float W80[12] = {y00.x, y00.y, y00.z, y00.w,
                                         y01.x, y01.y, y01.z, y01.w,
                                         y02.x, y02.y, y02.z, y02.w};
                        float C0[4] = {cv0.x, cv0.y, cv0.z, cv0.w};
                        float W41[8]  = {p10.x, p10.y, p10.z, p10.w,
                                         p11.x, p11.y, p11.z, p11.w};
                        float W81[12] = {y10.x, y10.y, y10.z, y10.w,
                                         y11.x, y11.y, y11.z, y11.w,
                                         y12.x, y12.y, y12.z, y12.w};
                        float C1[4] = {cv1.x, cv1.y, cv1.z, cv1.w};

                        float a0[4], a1r[4];
                        #pragma unroll
                        for (int s = 0; s < 4; s++) {
                            float u0 = fmaf(q4c[0], W40[s],     C0[s]);
                            float u1 = fmaf(q4c[1], W40[s + 1], q4c[2] * W40[s + 2]);
                            float u2 = fmaf(q4c[3], W40[s + 3], q4c[4] * W40[s + 4]);
                            float u3 = fmaf(q8c[0], W80[s],     q8c[1] * W80[s + 1]);
                            float u4 = fmaf(q8c[2], W80[s + 2], q8c[3] * W80[s + 3]);
                            float u5 = fmaf(q8c[4], W80[s + 4], q8c[5] * W80[s + 5]);
                            float u6 = fmaf(q8c[6], W80[s + 6], q8c[7] * W80[s + 7]);
                            float u7 = q8c[8] * W80[s + 8];
                            a0[s] = ((u0 + u1) + (u2 + u3)) + ((u4 + u5) + (u6 + u7));

                            float v0 = fmaf(q4c[0], W41[s],     C1[s]);
                            float v1 = fmaf(q4c[1], W41[s + 1], q4c[2] * W41[s + 2]);
                            float v2 = fmaf(q4c[3], W41[s + 3], q4c[4] * W41[s + 4]);
                            float v3 = fmaf(q8c[0], W81[s],     q8c[1] * W81[s + 1]);
                            float v4 = fmaf(q8c[2], W81[s + 2], q8c[3] * W81[s + 3]);
                            float v5 = fmaf(q8c[4], W81[s + 4], q8c[5] * W81[s + 5]);
                            float v6 = fmaf(q8c[6], W81[s + 6], q8c[7] * W81[s + 7]);
                            float v7 = q8c[8] * W81[s + 8];
                            a1r[s] = ((v0 + v1) + (v2 + v3)) + ((v4 + v5) + (v6 + v7));
                        }
                        float4 r0 = make_float4(a0[0], a0[1], a0[2], a0[3]);
                        float4 r1 = make_float4(a1r[0], a1r[1], a1r[2], a1r[3]);
                        *reinterpret_cast<float4*>(&A0[t0]) = r0;
                        *reinterpret_cast<float4*>(&A1[t0]) = r1;
                        *reinterpret_cast<float4*>(&orow0[t0]) = r0;  // fused STG
                        *reinterpret_cast<float4*>(&orow1[t0]) = r1;
                    }
                    if (base + Cq < T_LEN)   // no barrier after final chunk
                        asm volatile("bar.sync 1, %0;\n" :: "r"(nthr) : "memory");
                }
            }
            // inactive warps fall through to exit
        }
    } else {
        // ================= GENERIC PATH (j == 359): scalar, per row =========
        float q2g[3];
        q2g[0] = a2 * a2; q2g[1] = 2.f * a1 * a2; q2g[2] = a1 * a1;
        const int l20 = 2 * d1, l21 = d1 + d2, l22 = 2 * d2;
        int l4[5], lg[9];
        #pragma unroll
        for (int i = 0; i < 5; i++) l4[i] = i * d1 + (4 - i) * d2;
        #pragma unroll
        for (int i = 0; i < 9; i++) lg[i] = i * d1 + (8 - i) * d2;
        const int Cq = 8 * min(d1, d2);

        asm volatile("cp.async.wait_group 0;\n");
        __syncthreads();

        for (int r = 0; r < ROWS_PER_CTA; r++) {
            float* A = (r == 0) ? A0 : A1;
            float* B = (r == 0) ? B0 : B1;
            float* orow = (r == 0) ? orow0 : orow1;

            #pragma unroll 4
            for (int t = tid; t < T_LEN; t += NT)
                B[t] = fmaf(-a1, A[t - d1], fmaf(-a2, A[t - d2], A[t]));
            __syncthreads();

            #pragma unroll 4
            for (int t = tid; t < T_LEN; t += NT)
                A[t] = fmaf(q2g[2], B[t - l20],
                       fmaf(q2g[1], B[t - l21],
                       fmaf(q2g[0], B[t - l22], B[t])));
            __syncthreads();

            #pragma unroll 4
            for (int t = tid; t < T_LEN; t += NT) {
                float acc = A[t];
                #pragma unroll
                for (int i = 0; i < 5; i++) acc = fmaf(q4c[i], A[t - l4[i]], acc);
                B[t] = acc;
            }
            __syncthreads();

            for (int base = 0; base < T_LEN; base += Cq) {
                const int end = min(base + Cq, T_LEN);
                for (int t = base + tid; t < end; t += NT) {
                    float acc = B[t];
                    #pragma unroll
                    for (int i = 0; i < 9; i++) acc = fmaf(q8c[i], B[t - lg[i]], acc);
                    B[t] = acc;
                    orow[t] = acc;
                }
                __syncthreads();
            }
        }
    }
}

extern "C" void kernel_launch(void* const* d_in, const int* in_sizes, int n_in,
                              void* d_out, int out_size)
{
    const float* excitation = (const float*)d_in[0];  // (128,1,8192)
    const float* gumbel     = (const float*)d_in[1];  // (360,)
    const float* dparam     = (const float*)d_in[2];  // (360,)
    const float* fgain      = (const float*)d_in[3];  // (1,)
    const float* refl       = (const float*)d_in[4];  // (2,)
    float* out = (float*)d_out;                       // (128,1,8192)

    const int smem_bytes = ROWS_PER_CTA * ROW_STRIDE * sizeof(float); // ~184.8 KB
    cudaFuncSetAttribute(ks_resonator_kernel,
                         cudaFuncAttributeMaxDynamicSharedMemorySize, smem_bytes);

    ks_resonator_kernel<<<B_ROWS / ROWS_PER_CTA, NT, smem_bytes>>>(
        excitation, gumbel, dparam, fgain, refl, out);
}